// round 12
// baseline (speedup 1.0000x reference)
#include <cuda_runtime.h>
#include <cuda_fp16.h>
#include <math.h>
#include <stdint.h>

#define N_NODES 10000
#define N_EDGES 160000
#define ET (N_EDGES + N_NODES)

// ---------------- scratch (static __device__, no allocations) ----------------
__device__ __half g_h[(size_t)N_NODES * 1536];     // GAT linear output, fp16
__device__ __half g_linh[(size_t)N_NODES * 1024];  // skip-linear output, fp16
__device__ __half g_x1h[(size_t)N_NODES * 1024];
__device__ __half g_x2h[(size_t)N_NODES * 1024];
__device__ __half g_w2h[1024 * 1024];
__device__ __half g_lw2h[1024 * 1024];
__device__ __half g_w3h[1536 * 1024];
__device__ __half g_lw3h[256 * 1024];
__device__ float  g_as[N_NODES * 6];
__device__ float  g_ad[N_NODES * 6];
__device__ float  g_asp[N_NODES * 6 * 4];   // alpha partials (4 slots, single-writer)
__device__ float  g_adp[N_NODES * 6 * 4];
__device__ int    g_rowptr[N_NODES + 1];
__device__ int    g_cnt[N_NODES];
__device__ int    g_fill[N_NODES];
__device__ int    g_col[ET];

// ---------------- graph build ----------------
__global__ void k_count(const int* __restrict__ ei) {
    int i = blockIdx.x * blockDim.x + threadIdx.x;
    if (i >= ET) return;
    int d = (i < N_EDGES) ? ei[N_EDGES + i] : (i - N_EDGES);
    atomicAdd(&g_cnt[d], 1);
}

// single-block scan: 1024 threads x 10 sequential elements each
__global__ void k_scan_one() {
    const int t = threadIdx.x;
    const int lane = t & 31, w = t >> 5;
    const int base = t * 10;
    int vals[10];
    int s = 0;
#pragma unroll
    for (int k = 0; k < 10; k++) {
        int i = base + k;
        int v = (i < N_NODES) ? g_cnt[i] : 0;
        s += v;
        vals[k] = s;               // local inclusive
    }
    // warp inclusive scan of per-thread sums
    int x = s;
#pragma unroll
    for (int o = 1; o < 32; o <<= 1) {
        int y = __shfl_up_sync(0xffffffffu, x, o);
        if (lane >= o) x += y;
    }
    __shared__ int ws[32];
    if (lane == 31) ws[w] = x;
    __syncthreads();
    if (w == 0) {
        int v = ws[lane];
#pragma unroll
        for (int o = 1; o < 32; o <<= 1) {
            int y = __shfl_up_sync(0xffffffffu, v, o);
            if (lane >= o) v += y;
        }
        ws[lane] = v;              // inclusive warp totals
    }
    __syncthreads();
    int warp_excl = (w == 0) ? 0 : ws[w - 1];
    int thr_excl = warp_excl + (x - s);
#pragma unroll
    for (int k = 0; k < 10; k++) {
        int i = base + k;
        if (i < N_NODES) g_rowptr[i + 1] = thr_excl + vals[k];
    }
    if (t == 0) g_rowptr[0] = 0;
}

__global__ void k_scatter(const int* __restrict__ ei) {
    int i = blockIdx.x * blockDim.x + threadIdx.x;
    if (i >= ET) return;
    int s, d;
    if (i < N_EDGES) { s = ei[i]; d = ei[N_EDGES + i]; }
    else             { s = d = i - N_EDGES; }
    int pos = g_rowptr[d] + atomicAdd(&g_fill[d], 1);
    g_col[pos] = s;
}

// ---------------- fused fp32 -> fp16 weight conversion (float4 vectorized) ----
#define S_W2  (1024 * 1024)
#define S_LW2 (1024 * 1024)
#define S_W3  (1536 * 1024)
#define S_LW3 (256 * 1024)
#define F2H_TOTAL4 ((S_W2 + S_LW2 + S_W3 + S_LW3) / 4)

__global__ void k_f2h_all(const float* __restrict__ W2, const float* __restrict__ lw2,
                          const float* __restrict__ W3, const float* __restrict__ lw3) {
    int i = blockIdx.x * blockDim.x + threadIdx.x;   // float4 index
    if (i >= F2H_TOTAL4) return;
    const float* src;
    __half* dst;
    int off;
    if (i < S_W2 / 4)                      { src = W2;  dst = g_w2h;  off = i; }
    else if (i < (S_W2 + S_LW2) / 4)       { src = lw2; dst = g_lw2h; off = i - S_W2 / 4; }
    else if (i < (S_W2 + S_LW2 + S_W3) / 4){ src = W3;  dst = g_w3h;  off = i - (S_W2 + S_LW2) / 4; }
    else                                   { src = lw3; dst = g_lw3h; off = i - (S_W2 + S_LW2 + S_W3) / 4; }
    float4 v = *reinterpret_cast<const float4*>(src + 4 * off);
    uint2 o;
    __half2 a = __floats2half2_rn(v.x, v.y);
    __half2 b = __floats2half2_rn(v.z, v.w);
    o.x = *reinterpret_cast<uint32_t*>(&a);
    o.y = *reinterpret_cast<uint32_t*>(&b);
    *reinterpret_cast<uint2*>(dst + 4 * off) = o;
}

// ---------------- alpha partial fixup: g_as/g_ad = sum of 4 slots ----------------
__global__ void k_alpha_fix(int total) {    // total = N_NODES * H
    int i = blockIdx.x * blockDim.x + threadIdx.x;
    if (i >= total) return;
    float4 s = *reinterpret_cast<const float4*>(g_asp + 4 * i);
    float4 d = *reinterpret_cast<const float4*>(g_adp + 4 * i);
    g_as[i] = (s.x + s.y) + (s.z + s.w);
    g_ad[i] = (d.x + d.y) + (d.z + d.w);
}

// -------- scalar SGEMM dual-output (layer 1, K=14): [C1|C2] = A * [B1|B2]^T --------
// First half also emits alpha partials (slot = column-quarter of the head).
__global__ void sgemm_dual(const float* __restrict__ A,
                           const float* __restrict__ B1, const float* __restrict__ B2,
                           __half* __restrict__ C1, __half* __restrict__ C2,
                           const float* __restrict__ a_s, const float* __restrict__ a_d,
                           int M, int N1, int N2, int K) {
    const int BM = 128, BN = 64, BK = 16;
    __shared__ float As[BK][BM + 4];
    __shared__ float Bs[BK][BN + 4];
    int bnG = blockIdx.x * BN;
    bool second = bnG >= N1;
    const float* B = second ? B2 : B1;
    __half* C = second ? C2 : C1;
    int bn = second ? bnG - N1 : bnG;
    int Nc = second ? N2 : N1;
    const int H = N1 >> 8;

    int bm = blockIdx.y * BM;
    int t = threadIdx.x;
    int tx = t & 15, ty = t >> 4;
    float acc[8][4];
#pragma unroll
    for (int i = 0; i < 8; i++)
#pragma unroll
        for (int j = 0; j < 4; j++) acc[i][j] = 0.f;
    for (int k0 = 0; k0 < K; k0 += BK) {
#pragma unroll
        for (int i = 0; i < 8; i++) {
            int idx = t + i * 256;
            int r = idx >> 4, kk = idx & 15;
            int gr = bm + r, gk = k0 + kk;
            As[kk][r] = (gr < M && gk < K) ? A[(size_t)gr * K + gk] : 0.f;
        }
#pragma unroll
        for (int i = 0; i < 4; i++) {
            int idx = t + i * 256;
            int r = idx >> 4, kk = idx & 15;
            int gr = bn + r, gk = k0 + kk;
            Bs[kk][r] = (gr < Nc && gk < K) ? B[(size_t)gr * K + gk] : 0.f;
        }
        __syncthreads();
#pragma unroll
        for (int kk = 0; kk < BK; kk++) {
            float a[8], b[4];
#pragma unroll
            for (int i = 0; i < 8; i++) a[i] = As[kk][ty * 8 + i];
#pragma unroll
            for (int j = 0; j < 4; j++) b[j] = Bs[kk][tx * 4 + j];
#pragma unroll
            for (int i = 0; i < 8; i++)
#pragma unroll
                for (int j = 0; j < 4; j++) acc[i][j] = fmaf(a[i], b[j], acc[i][j]);
        }
        __syncthreads();
    }
#pragma unroll
    for (int i = 0; i < 8; i++) {
        int r = bm + ty * 8 + i;
        if (r >= M) continue;
        int c = bn + tx * 4;
        __half2 h0 = __floats2half2_rn(acc[i][0], acc[i][1]);
        __half2 h1 = __floats2half2_rn(acc[i][2], acc[i][3]);
        uint2 o;
        o.x = *reinterpret_cast<uint32_t*>(&h0);
        o.y = *reinterpret_cast<uint32_t*>(&h1);
        *reinterpret_cast<uint2*>(C + (size_t)r * Nc + c) = o;
    }

    // alpha partials (first half only); single writer per (row, slot)
    if (!second) {
        int head = bnG >> 8;
        int slot = (bnG >> 6) & 3;
        float av_s[4], av_d[4];
        int base = (bnG & 255) + tx * 4;
#pragma unroll
        for (int j = 0; j < 4; j++) {
            av_s[j] = a_s[head * 256 + base + j];
            av_d[j] = a_d[head * 256 + base + j];
        }
#pragma unroll
        for (int i = 0; i < 8; i++) {
            float ps = acc[i][0] * av_s[0] + acc[i][1] * av_s[1] +
                       acc[i][2] * av_s[2] + acc[i][3] * av_s[3];
            float pd = acc[i][0] * av_d[0] + acc[i][1] * av_d[1] +
                       acc[i][2] * av_d[2] + acc[i][3] * av_d[3];
#pragma unroll
            for (int o = 1; o < 16; o <<= 1) {
                ps += __shfl_xor_sync(0xffffffffu, ps, o);
                pd += __shfl_xor_sync(0xffffffffu, pd, o);
            }
            int r = bm + ty * 8 + i;
            if (tx == 0 && r < M) {
                g_asp[(r * H + head) * 4 + slot] = ps;
                g_adp[(r * H + head) * 4 + slot] = pd;
            }
        }
    }
}

// ====== fp16 tensor-core dual GEMM (mma.sync m16n8k16): [C1|C2] = A*[B1|B2]^T ======
// 256 threads, 64x128 CTA tile, warp 16x64 (8 warps, 4m x 2n), 4-stage cp.async,
// single-barrier mainloop, 3 CTAs/SM. First half emits alpha partials.
// K%32==0, N1%128==0, N2%128==0, K/32>=4.

#define HBK 32
#define HSTRIDE 40
#define HSTAGE_BYTES ((64 + 128) * HSTRIDE * 2)   // A(64 rows)+B(128 rows) = 15360
#define HB_OFF (64 * HSTRIDE * 2)                 // B offset within stage = 5120
#define HSMEM_BYTES (4 * HSTAGE_BYTES)            // 61440

__device__ __forceinline__ void mma_f16(float c[4], const uint32_t a[4], const uint32_t b[2]) {
    asm volatile(
        "mma.sync.aligned.m16n8k16.row.col.f32.f16.f16.f32 "
        "{%0,%1,%2,%3}, {%4,%5,%6,%7}, {%8,%9}, {%0,%1,%2,%3};"
        : "+f"(c[0]), "+f"(c[1]), "+f"(c[2]), "+f"(c[3])
        : "r"(a[0]), "r"(a[1]), "r"(a[2]), "r"(a[3]), "r"(b[0]), "r"(b[1]));
}
__device__ __forceinline__ void ldsm_x4(uint32_t r[4], uint32_t saddr) {
    asm volatile("ldmatrix.sync.aligned.m8n8.x4.shared.b16 {%0,%1,%2,%3}, [%4];"
                 : "=r"(r[0]), "=r"(r[1]), "=r"(r[2]), "=r"(r[3]) : "r"(saddr));
}
__device__ __forceinline__ void cp_async16(uint32_t saddr, const void* gaddr) {
    asm volatile("cp.async.cg.shared.global [%0], [%1], 16;" :: "r"(saddr), "l"(gaddr));
}
__device__ __forceinline__ void cp_commit() { asm volatile("cp.async.commit_group;"); }
template <int N_> __device__ __forceinline__ void cp_wait() {
    asm volatile("cp.async.wait_group %0;" :: "n"(N_));
}
static __device__ __forceinline__ uint32_t smem_u32(const void* p) {
    uint32_t a;
    asm("{ .reg .u64 t; cvta.to.shared.u64 t, %1; cvt.u32.u64 %0, t; }" : "=r"(a) : "l"(p));
    return a;
}

__global__ __launch_bounds__(256, 3)
void gemm_f16_dual(const __half* __restrict__ A,
                   const __half* __restrict__ B1, const __half* __restrict__ B2,
                   __half* __restrict__ C1, __half* __restrict__ C2,
                   const float* __restrict__ a_s, const float* __restrict__ a_d,
                   int M, int N1, int N2, int K) {
    extern __shared__ __half hsm[];
    const uint32_t s0 = smem_u32(hsm);

    const int bnG = blockIdx.x * 128;
    const bool second = bnG >= N1;
    const __half* B = second ? B2 : B1;
    __half* C = second ? C2 : C1;
    const int bn = second ? bnG - N1 : bnG;
    const int Nc = second ? N2 : N1;
    const int H = N1 >> 8;

    const int bm = blockIdx.y * 64;
    const int t = threadIdx.x;
    const int w = t >> 5, lane = t & 31;
    const int wm = (w >> 1) * 16;   // 0/16/32/48
    const int wn = (w & 1) * 64;    // 0/64
    const int g = lane >> 2;
    const int r = lane & 3;

    const int sub = lane >> 3;
    const int frow = (sub & 1) * 8 + (lane & 7);
    const int fkof = (sub >> 1) * 8;

    float acc[8][4];
#pragma unroll
    for (int ni = 0; ni < 8; ni++)
#pragma unroll
        for (int q = 0; q < 4; q++) acc[ni][q] = 0.f;

    const int nIter = K / HBK;

    // per-thread load slots: 1 A chunk (rows 0..63) + 2 B chunks (rows 0..127)
    const int rA = t >> 2,        kA = (t & 3) * 8;
    const int rB0 = t >> 2,       kB0 = (t & 3) * 8;
    const int rB1 = 64 + (t >> 2),kB1 = (t & 3) * 8;
    const __half* gA0 = A + (size_t)min(bm + rA, M - 1) * K + kA;
    const __half* gB0 = B + (size_t)(bn + rB0) * K + kB0;
    const __half* gB1 = B + (size_t)(bn + rB1) * K + kB1;
    const uint32_t saA = (uint32_t)(rA * HSTRIDE + kA) * 2;
    const uint32_t saB0 = HB_OFF + (uint32_t)(rB0 * HSTRIDE + kB0) * 2;
    const uint32_t saB1 = HB_OFF + (uint32_t)(rB1 * HSTRIDE + kB1) * 2;

    auto load_stage = [&](int j) {
        const int s = j & 3;
        const int k0 = j * HBK;
        const uint32_t base = s0 + s * HSTAGE_BYTES;
        cp_async16(base + saA, gA0 + k0);
        cp_async16(base + saB0, gB0 + k0);
        cp_async16(base + saB1, gB1 + k0);
        cp_commit();
    };

    load_stage(0);
    load_stage(1);
    load_stage(2);

    for (int j = 0; j < nIter; j++) {
        const int s = j & 3;
        if (j + 2 < nIter)      cp_wait<2>();
        else if (j + 1 < nIter) cp_wait<1>();
        else                    cp_wait<0>();
        __syncthreads();
        if (j + 3 < nIter) load_stage(j + 3);

        const uint32_t aS = s0 + s * HSTAGE_BYTES;
        const uint32_t bS = aS + HB_OFF;
#pragma unroll
        for (int ks = 0; ks < 2; ks++) {
            const int kb = ks * 16;
            uint32_t af[4], bf[8][2];
            ldsm_x4(af, aS + ((wm + frow) * HSTRIDE + kb + fkof) * 2);
#pragma unroll
            for (int np = 0; np < 4; np++) {
                uint32_t rr[4];
                ldsm_x4(rr, bS + ((wn + np * 16 + frow) * HSTRIDE + kb + fkof) * 2);
                bf[2 * np + 0][0] = rr[0];
                bf[2 * np + 1][0] = rr[1];
                bf[2 * np + 0][1] = rr[2];
                bf[2 * np + 1][1] = rr[3];
            }
#pragma unroll
            for (int ni = 0; ni < 8; ni++)
                mma_f16(acc[ni], af, bf[ni]);
        }
    }

    // epilogue (fp16 both outputs)
    {
        int row0 = bm + wm + g;
        int row1 = row0 + 8;
#pragma unroll
        for (int ni = 0; ni < 8; ni++) {
            int col = bn + wn + ni * 8 + 2 * r;
            if (row0 < M)
                *reinterpret_cast<__half2*>(C + (size_t)row0 * Nc + col) =
                    __floats2half2_rn(acc[ni][0], acc[ni][1]);
            if (row1 < M)
                *reinterpret_cast<__half2*>(C + (size_t)row1 * Nc + col) =
                    __floats2half2_rn(acc[ni][2], acc[ni][3]);
        }
    }

    // alpha partials (first half only); slot = 2*(column-128-tile) + warp-n-half
    if (!second) {
        const int head = bnG >> 8;
        const int slot = ((bnG >> 7) & 1) * 2 + (wn >> 6);
        float av_s[16], av_d[16];
        const int base = head * 256 + (bnG & 255) + wn + 2 * r;
#pragma unroll
        for (int ni = 0; ni < 8; ni++) {
#pragma unroll
            for (int q = 0; q < 2; q++) {
                av_s[ni * 2 + q] = a_s[base + ni * 8 + q];
                av_d[ni * 2 + q] = a_d[base + ni * 8 + q];
            }
        }
        float ps[2] = {0.f, 0.f}, pd[2] = {0.f, 0.f};   // rows: row0, row1
#pragma unroll
        for (int ni = 0; ni < 8; ni++) {
            ps[0] += acc[ni][0] * av_s[ni * 2] + acc[ni][1] * av_s[ni * 2 + 1];
            ps[1] += acc[ni][2] * av_s[ni * 2] + acc[ni][3] * av_s[ni * 2 + 1];
            pd[0] += acc[ni][0] * av_d[ni * 2] + acc[ni][1] * av_d[ni * 2 + 1];
            pd[1] += acc[ni][2] * av_d[ni * 2] + acc[ni][3] * av_d[ni * 2 + 1];
        }
#pragma unroll
        for (int o = 1; o < 4; o <<= 1) {
#pragma unroll
            for (int k = 0; k < 2; k++) {
                ps[k] += __shfl_xor_sync(0xffffffffu, ps[k], o);
                pd[k] += __shfl_xor_sync(0xffffffffu, pd[k], o);
            }
        }
        if (r == 0) {
            int row0 = bm + wm + g;
            int row1 = row0 + 8;
            if (row0 < M) {
                g_asp[(row0 * H + head) * 4 + slot] = ps[0];
                g_adp[(row0 * H + head) * 4 + slot] = pd[0];
            }
            if (row1 < M) {
                g_asp[(row1 * H + head) * 4 + slot] = ps[1];
                g_adp[(row1 * H + head) * 4 + slot] = pd[1];
            }
        }
    }
}

__device__ __forceinline__ float lrelu(float x) { return x > 0.f ? x : 0.2f * x; }

// ---------------- fused segment-softmax + aggregation + epilogue ----------------
template <int H, bool MEAN, bool APPLY_ELU, typename OT>
__global__ void gat_agg(const float* __restrict__ bgat, const float* __restrict__ lb,
                        OT* __restrict__ out) {
    int n = blockIdx.x;
    int t = threadIdx.x;
    int start = g_rowptr[n];
    int deg = g_rowptr[n + 1] - start;

    __shared__ float s_m[H], s_dinv[H];
    int w = t >> 5, lane = t & 31;
    if (w < H) {
        float ad = g_ad[n * H + w];
        float mx = -1e30f;
        for (int j = lane; j < deg; j += 32)
            mx = fmaxf(mx, lrelu(g_as[g_col[start + j] * H + w] + ad));
#pragma unroll
        for (int o = 16; o; o >>= 1) mx = fmaxf(mx, __shfl_xor_sync(0xffffffffu, mx, o));
        float sum = 0.f;
        for (int j = lane; j < deg; j += 32)
            sum += __expf(lrelu(g_as[g_col[start + j] * H + w] + ad) - mx);
#pragma unroll
        for (int o = 16; o; o >>= 1) sum += __shfl_xor_sync(0xffffffffu, sum, o);
        if (lane == 0) { s_m[w] = mx; s_dinv[w] = 1.f / (sum + 1e-16f); }
    }
    __syncthreads();

    const int CH = 32;
    __shared__ float s_coef[CH][H];
    __shared__ int   s_src[CH];
    const int hA = t >> 6;                 // head of channels 4t..4t+3
    const int hB = 4 + (t >> 7);           // head of channels 1024+2t (H==6)

    float2 accA0 = make_float2(0.f, 0.f);
    float2 accA1 = make_float2(0.f, 0.f);
    float2 accB  = make_float2(0.f, 0.f);

    for (int cs = 0; cs < deg; cs += CH) {
        int cnt = min(CH, deg - cs);
        if (t < cnt) s_src[t] = g_col[start + cs + t];
        for (int idx = t; idx < cnt * H; idx += 256) {
            int j = idx / H, h = idx - j * H;
            int s = g_col[start + cs + j];
            float ee = lrelu(g_as[s * H + h] + g_ad[n * H + h]);
            s_coef[j][h] = __expf(ee - s_m[h]) * s_dinv[h];
        }
        __syncthreads();
        for (int j = 0; j < cnt; j++) {
            const __half* row = g_h + (size_t)s_src[j] * (H * 256);
            uint2 va = *reinterpret_cast<const uint2*>(row + 4 * t);
            float cA = s_coef[j][hA];
            float2 f0 = __half22float2(*reinterpret_cast<__half2*>(&va.x));
            float2 f1 = __half22float2(*reinterpret_cast<__half2*>(&va.y));
            accA0.x = fmaf(f0.x, cA, accA0.x);
            accA0.y = fmaf(f0.y, cA, accA0.y);
            accA1.x = fmaf(f1.x, cA, accA1.x);
            accA1.y = fmaf(f1.y, cA, accA1.y);
            if (H == 6) {
                __half2 vb = *reinterpret_cast<const __half2*>(row + 1024 + 2 * t);
                float cB = s_coef[j][hB];
                float2 fb = __half22float2(vb);
                accB.x = fmaf(fb.x, cB, accB.x);
                accB.y = fmaf(fb.y, cB, accB.y);
            }
        }
        __syncthreads();
    }

    if (MEAN) {
        __shared__ float s_sum[256];
        s_sum[t] = 0.f;
        __syncthreads();
        int cA = (4 * t) & 255;
        atomicAdd(&s_sum[cA + 0], accA0.x);
        atomicAdd(&s_sum[cA + 1], accA0.y);
        atomicAdd(&s_sum[cA + 2], accA1.x);
        atomicAdd(&s_sum[cA + 3], accA1.y);
        int cB = (2 * t) & 255;
        atomicAdd(&s_sum[cB + 0], accB.x);
        atomicAdd(&s_sum[cB + 1], accB.y);
        __syncthreads();
        float ln = __half2float(g_linh[(size_t)n * 256 + t]);
        float v = s_sum[t] * (1.f / (float)H) + bgat[t] + ln + lb[t];
        reinterpret_cast<float*>(out)[(size_t)n * 256 + t] = v;
    } else {
        int c = 4 * t;
        float4 bg = *reinterpret_cast<const float4*>(bgat + c);
        float4 lb4 = *reinterpret_cast<const float4*>(lb + c);
        uint2 lv = *reinterpret_cast<const uint2*>(g_linh + (size_t)n * 1024 + c);
        float2 l0 = __half22float2(*reinterpret_cast<__half2*>(&lv.x));
        float2 l1 = __half22float2(*reinterpret_cast<__half2*>(&lv.y));
        float v0 = accA0.x + bg.x + l0.x + lb4.x;
        float v1 = accA0.y + bg.y + l0.y + lb4.y;
        float v2 = accA1.x + bg.z + l1.x + lb4.z;
        float v3 = accA1.y + bg.w + l1.y + lb4.w;
        if (APPLY_ELU) {
            v0 = v0 > 0.f ? v0 : (__expf(v0) - 1.f);
            v1 = v1 > 0.f ? v1 : (__expf(v1) - 1.f);
            v2 = v2 > 0.f ? v2 : (__expf(v2) - 1.f);
            v3 = v3 > 0.f ? v3 : (__expf(v3) - 1.f);
        }
        uint2 o;
        __half2 ha = __floats2half2_rn(v0, v1);
        __half2 hb = __floats2half2_rn(v2, v3);
        o.x = *reinterpret_cast<uint32_t*>(&ha);
        o.y = *reinterpret_cast<uint32_t*>(&hb);
        *reinterpret_cast<uint2*>(reinterpret_cast<__half*>(out) + (size_t)n * 1024 + c) = o;
    }
}

// ---------------- host launcher ----------------
static inline void run_gemm_dual_tc(const __half* A, const __half* B1, const __half* B2,
                                    __half* C1, __half* C2,
                                    const float* a_s, const float* a_d,
                                    int M, int N1, int N2, int K) {
    dim3 grid((N1 + N2) / 128, (M + 63) / 64);
    gemm_f16_dual<<<grid, 256, HSMEM_BYTES>>>(A, B1, B2, C1, C2, a_s, a_d, M, N1, N2, K);
}

extern "C" void kernel_launch(void* const* d_in, const int* in_sizes, int n_in,
                              void* d_out, int out_size) {
    const float* x   = (const float*)d_in[0];
    const int*   ei  = (const int*)d_in[1];
    const float* W1  = (const float*)d_in[2];
    const float* a1s = (const float*)d_in[3];
    const float* a1d = (const float*)d_in[4];
    const float* b1  = (const float*)d_in[5];
    const float* lw1 = (const float*)d_in[6];
    const float* lb1 = (const float*)d_in[7];
    const float* W2  = (const float*)d_in[8];
    const float* a2s = (const float*)d_in[9];
    const float* a2d = (const float*)d_in[10];
    const float* b2  = (const float*)d_in[11];
    const float* lw2 = (const float*)d_in[12];
    const float* lb2 = (const float*)d_in[13];
    const float* W3  = (const float*)d_in[14];
    const float* a3s = (const float*)d_in[15];
    const float* a3d = (const float*)d_in[16];
    const float* b3  = (const float*)d_in[17];
    const float* lw3 = (const float*)d_in[18];
    const float* lb3 = (const float*)d_in[19];
    float* out = (float*)d_out;

    cudaFuncSetAttribute(gemm_f16_dual, cudaFuncAttributeMaxDynamicSharedMemorySize,
                         HSMEM_BYTES);

    void *p_h, *p_lin, *p_x1h, *p_x2h;
    cudaGetSymbolAddress(&p_h, g_h);
    cudaGetSymbolAddress(&p_lin, g_linh);
    cudaGetSymbolAddress(&p_x1h, g_x1h);
    cudaGetSymbolAddress(&p_x2h, g_x2h);
    __half* h    = (__half*)p_h;
    __half* lin  = (__half*)p_lin;
    __half* x1h  = (__half*)p_x1h;
    __half* x2h  = (__half*)p_x2h;

    void *p_w2h, *p_lw2h, *p_w3h, *p_lw3h;
    cudaGetSymbolAddress(&p_w2h, g_w2h);
    cudaGetSymbolAddress(&p_lw2h, g_lw2h);
    cudaGetSymbolAddress(&p_w3h, g_w3h);
    cudaGetSymbolAddress(&p_lw3h, g_lw3h);
    __half* w2h  = (__half*)p_w2h;
    __half* lw2h = (__half*)p_lw2h;
    __half* w3h  = (__half*)p_w3h;
    __half* lw3h = (__half*)p_lw3h;

    void *p_cnt, *p_fill;
    cudaGetSymbolAddress(&p_cnt, g_cnt);
    cudaGetSymbolAddress(&p_fill, g_fill);

    // build CSR by dst (edges + self-loops)
    cudaMemsetAsync(p_cnt, 0, N_NODES * sizeof(int));
    cudaMemsetAsync(p_fill, 0, N_NODES * sizeof(int));
    k_count<<<(ET + 255) / 256, 256>>>(ei);
    k_scan_one<<<1, 1024>>>();
    k_scatter<<<(ET + 255) / 256, 256>>>(ei);

    // convert all weights to fp16 (one fused launch)
    k_f2h_all<<<(F2H_TOTAL4 + 255) / 256, 256>>>(W2, lw2, W3, lw3);

    // ---- layer 1: 14 -> 4x256, concat, +skip, ELU ----
    {
        dim3 grid((1024 + 1024) / 64, (N_NODES + 127) / 128);
        sgemm_dual<<<grid, 256>>>(x, W1, lw1, h, lin, a1s, a1d, N_NODES, 1024, 1024, 14);
    }
    k_alpha_fix<<<(N_NODES * 4 + 255) / 256, 256>>>(N_NODES * 4);
    gat_agg<4, false, true, __half><<<N_NODES, 256>>>(b1, lb1, x1h);

    // ---- layer 2: 1024 -> 4x256, concat, +skip, ELU ----
    run_gemm_dual_tc(x1h, w2h, lw2h, h, lin, a2s, a2d, N_NODES, 1024, 1024, 1024);
    k_alpha_fix<<<(N_NODES * 4 + 255) / 256, 256>>>(N_NODES * 4);
    gat_agg<4, false, true, __half><<<N_NODES, 256>>>(b2, lb2, x2h);

    // ---- layer 3: 1024 -> mean of 6x256, +skip, no ELU ----
    run_gemm_dual_tc(x2h, w3h, lw3h, h, lin, a3s, a3d, N_NODES, 1536, 256, 1024);
    k_alpha_fix<<<(N_NODES * 6 + 255) / 256, 256>>>(N_NODES * 6);
    gat_agg<6, true, false, float><<<N_NODES, 256>>>(b3, lb3, out);
}

// round 13
// speedup vs baseline: 1.0343x; 1.0343x over previous
#include <cuda_runtime.h>
#include <cuda_fp16.h>
#include <math.h>
#include <stdint.h>

#define N_NODES 10000
#define N_EDGES 160000
#define ET (N_EDGES + N_NODES)

// ---------------- scratch (static __device__, no allocations) ----------------
__device__ __half g_h[(size_t)N_NODES * 1536];     // GAT linear output, fp16
__device__ __half g_linh[(size_t)N_NODES * 1024];  // skip-linear output, fp16
__device__ __half g_x1h[(size_t)N_NODES * 1024];
__device__ __half g_x2h[(size_t)N_NODES * 1024];
__device__ __half g_w2h[1024 * 1024];
__device__ __half g_lw2h[1024 * 1024];
__device__ __half g_w3h[1536 * 1024];
__device__ __half g_lw3h[256 * 1024];
__device__ float  g_as[N_NODES * 6];
__device__ float  g_ad[N_NODES * 6];
__device__ float  g_asp[N_NODES * 6 * 4];   // alpha partials (4 slots, single-writer)
__device__ float  g_adp[N_NODES * 6 * 4];
__device__ int    g_rowptr[N_NODES + 1];
__device__ int    g_cnt[N_NODES];
__device__ int    g_fill[N_NODES];
__device__ int    g_col[ET];

// ---------------- single-block scan: 1024 threads x 10 elements ----------------
__global__ void k_scan_one() {
    const int t = threadIdx.x;
    const int lane = t & 31, w = t >> 5;
    const int base = t * 10;
    int vals[10];
    int s = 0;
#pragma unroll
    for (int k = 0; k < 10; k++) {
        int i = base + k;
        int v = (i < N_NODES) ? g_cnt[i] : 0;
        s += v;
        vals[k] = s;
    }
    int x = s;
#pragma unroll
    for (int o = 1; o < 32; o <<= 1) {
        int y = __shfl_up_sync(0xffffffffu, x, o);
        if (lane >= o) x += y;
    }
    __shared__ int ws[32];
    if (lane == 31) ws[w] = x;
    __syncthreads();
    if (w == 0) {
        int v = ws[lane];
#pragma unroll
        for (int o = 1; o < 32; o <<= 1) {
            int y = __shfl_up_sync(0xffffffffu, v, o);
            if (lane >= o) v += y;
        }
        ws[lane] = v;
    }
    __syncthreads();
    int warp_excl = (w == 0) ? 0 : ws[w - 1];
    int thr_excl = warp_excl + (x - s);
#pragma unroll
    for (int k = 0; k < 10; k++) {
        int i = base + k;
        if (i < N_NODES) g_rowptr[i + 1] = thr_excl + vals[k];
    }
    if (t == 0) g_rowptr[0] = 0;
}

// ---------------- fused fp32->fp16 weight conversion + edge counting ----------
#define S_W2  (1024 * 1024)
#define S_LW2 (1024 * 1024)
#define S_W3  (1536 * 1024)
#define S_LW3 (256 * 1024)
#define F2H_TOTAL4 ((S_W2 + S_LW2 + S_W3 + S_LW3) / 4)
#define F2H_BLOCKS ((F2H_TOTAL4 + 255) / 256)      // 3840
#define CNT_BLOCKS ((ET + 255) / 256)              // 665

__global__ void k_f2h_count(const float* __restrict__ W2, const float* __restrict__ lw2,
                            const float* __restrict__ W3, const float* __restrict__ lw3,
                            const int* __restrict__ ei) {
    if (blockIdx.x >= F2H_BLOCKS) {
        int i = (blockIdx.x - F2H_BLOCKS) * blockDim.x + threadIdx.x;
        if (i < ET) {
            int d = (i < N_EDGES) ? ei[N_EDGES + i] : (i - N_EDGES);
            atomicAdd(&g_cnt[d], 1);
        }
        return;
    }
    int i = blockIdx.x * blockDim.x + threadIdx.x;
    if (i >= F2H_TOTAL4) return;
    const float* src;
    __half* dst;
    int off;
    if (i < S_W2 / 4)                      { src = W2;  dst = g_w2h;  off = i; }
    else if (i < (S_W2 + S_LW2) / 4)       { src = lw2; dst = g_lw2h; off = i - S_W2 / 4; }
    else if (i < (S_W2 + S_LW2 + S_W3) / 4){ src = W3;  dst = g_w3h;  off = i - (S_W2 + S_LW2) / 4; }
    else                                   { src = lw3; dst = g_lw3h; off = i - (S_W2 + S_LW2 + S_W3) / 4; }
    float4 v = *reinterpret_cast<const float4*>(src + 4 * off);
    uint2 o;
    __half2 a = __floats2half2_rn(v.x, v.y);
    __half2 b = __floats2half2_rn(v.z, v.w);
    o.x = *reinterpret_cast<uint32_t*>(&a);
    o.y = *reinterpret_cast<uint32_t*>(&b);
    *reinterpret_cast<uint2*>(dst + 4 * off) = o;
}

// ---------------- alpha partial fixup: g_as/g_ad = sum of 4 slots ----------------
__global__ void k_alpha_fix(int total) {    // total = N_NODES * H
    int i = blockIdx.x * blockDim.x + threadIdx.x;
    if (i >= total) return;
    float4 s = *reinterpret_cast<const float4*>(g_asp + 4 * i);
    float4 d = *reinterpret_cast<const float4*>(g_adp + 4 * i);
    g_as[i] = (s.x + s.y) + (s.z + s.w);
    g_ad[i] = (d.x + d.y) + (d.z + d.w);
}

// -------- scalar SGEMM dual-output (layer 1, K=14) + fused edge scatter --------
// grid.y rows beyond the M tiles perform CSR scatter (overlapped with the GEMM).
__global__ void sgemm_dual(const float* __restrict__ A,
                           const float* __restrict__ B1, const float* __restrict__ B2,
                           __half* __restrict__ C1, __half* __restrict__ C2,
                           const float* __restrict__ a_s, const float* __restrict__ a_d,
                           const int* __restrict__ ei,
                           int M, int N1, int N2, int K) {
    const int BM = 128, BN = 64, BK = 16;
    const int mtiles = (M + BM - 1) / BM;
    if ((int)blockIdx.y >= mtiles) {
        // scatter tail blocks
        int sb = (blockIdx.y - mtiles) * gridDim.x + blockIdx.x;
        int i = sb * 256 + threadIdx.x;
        if (i < ET) {
            int s, d;
            if (i < N_EDGES) { s = ei[i]; d = ei[N_EDGES + i]; }
            else             { s = d = i - N_EDGES; }
            int pos = g_rowptr[d] + atomicAdd(&g_fill[d], 1);
            g_col[pos] = s;
        }
        return;
    }

    __shared__ float As[BK][BM + 4];
    __shared__ float Bs[BK][BN + 4];
    int bnG = blockIdx.x * BN;
    bool second = bnG >= N1;
    const float* B = second ? B2 : B1;
    __half* C = second ? C2 : C1;
    int bn = second ? bnG - N1 : bnG;
    int Nc = second ? N2 : N1;
    const int H = N1 >> 8;

    int bm = blockIdx.y * BM;
    int t = threadIdx.x;
    int tx = t & 15, ty = t >> 4;
    float acc[8][4];
#pragma unroll
    for (int i = 0; i < 8; i++)
#pragma unroll
        for (int j = 0; j < 4; j++) acc[i][j] = 0.f;
    for (int k0 = 0; k0 < K; k0 += BK) {
#pragma unroll
        for (int i = 0; i < 8; i++) {
            int idx = t + i * 256;
            int r = idx >> 4, kk = idx & 15;
            int gr = bm + r, gk = k0 + kk;
            As[kk][r] = (gr < M && gk < K) ? A[(size_t)gr * K + gk] : 0.f;
        }
#pragma unroll
        for (int i = 0; i < 4; i++) {
            int idx = t + i * 256;
            int r = idx >> 4, kk = idx & 15;
            int gr = bn + r, gk = k0 + kk;
            Bs[kk][r] = (gr < Nc && gk < K) ? B[(size_t)gr * K + gk] : 0.f;
        }
        __syncthreads();
#pragma unroll
        for (int kk = 0; kk < BK; kk++) {
            float a[8], b[4];
#pragma unroll
            for (int i = 0; i < 8; i++) a[i] = As[kk][ty * 8 + i];
#pragma unroll
            for (int j = 0; j < 4; j++) b[j] = Bs[kk][tx * 4 + j];
#pragma unroll
            for (int i = 0; i < 8; i++)
#pragma unroll
                for (int j = 0; j < 4; j++) acc[i][j] = fmaf(a[i], b[j], acc[i][j]);
        }
        __syncthreads();
    }
#pragma unroll
    for (int i = 0; i < 8; i++) {
        int r = bm + ty * 8 + i;
        if (r >= M) continue;
        int c = bn + tx * 4;
        __half2 h0 = __floats2half2_rn(acc[i][0], acc[i][1]);
        __half2 h1 = __floats2half2_rn(acc[i][2], acc[i][3]);
        uint2 o;
        o.x = *reinterpret_cast<uint32_t*>(&h0);
        o.y = *reinterpret_cast<uint32_t*>(&h1);
        *reinterpret_cast<uint2*>(C + (size_t)r * Nc + c) = o;
    }

    // alpha partials (first half only); single writer per (row, slot)
    if (!second) {
        int head = bnG >> 8;
        int slot = (bnG >> 6) & 3;
        float av_s[4], av_d[4];
        int base = (bnG & 255) + tx * 4;
#pragma unroll
        for (int j = 0; j < 4; j++) {
            av_s[j] = a_s[head * 256 + base + j];
            av_d[j] = a_d[head * 256 + base + j];
        }
#pragma unroll
        for (int i = 0; i < 8; i++) {
            float ps = acc[i][0] * av_s[0] + acc[i][1] * av_s[1] +
                       acc[i][2] * av_s[2] + acc[i][3] * av_s[3];
            float pd = acc[i][0] * av_d[0] + acc[i][1] * av_d[1] +
                       acc[i][2] * av_d[2] + acc[i][3] * av_d[3];
#pragma unroll
            for (int o = 1; o < 16; o <<= 1) {
                ps += __shfl_xor_sync(0xffffffffu, ps, o);
                pd += __shfl_xor_sync(0xffffffffu, pd, o);
            }
            int r = bm + ty * 8 + i;
            if (tx == 0 && r < M) {
                g_asp[(r * H + head) * 4 + slot] = ps;
                g_adp[(r * H + head) * 4 + slot] = pd;
            }
        }
    }
}

// ====== fp16 tensor-core dual GEMM (mma.sync m16n8k16): [C1|C2] = A*[B1|B2]^T ======
// 256 threads, 128x128 CTA tile, warp 32x64 (8 warps, 4x2), 4-stage cp.async,
// single-barrier mainloop, 2 CTAs/SM. First half emits alpha partials.
// K%32==0, N1%128==0, N2%128==0, K/32>=4.

#define HBK 32
#define HSTRIDE 40
#define HSTAGE_BYTES (2 * 128 * HSTRIDE * 2)     // A + B per stage = 20480
#define HSMEM_BYTES  (4 * HSTAGE_BYTES)          // 81920

__device__ __forceinline__ void mma_f16(float c[4], const uint32_t a[4], const uint32_t b[2]) {
    asm volatile(
        "mma.sync.aligned.m16n8k16.row.col.f32.f16.f16.f32 "
        "{%0,%1,%2,%3}, {%4,%5,%6,%7}, {%8,%9}, {%0,%1,%2,%3};"
        : "+f"(c[0]), "+f"(c[1]), "+f"(c[2]), "+f"(c[3])
        : "r"(a[0]), "r"(a[1]), "r"(a[2]), "r"(a[3]), "r"(b[0]), "r"(b[1]));
}
__device__ __forceinline__ void ldsm_x4(uint32_t r[4], uint32_t saddr) {
    asm volatile("ldmatrix.sync.aligned.m8n8.x4.shared.b16 {%0,%1,%2,%3}, [%4];"
                 : "=r"(r[0]), "=r"(r[1]), "=r"(r[2]), "=r"(r[3]) : "r"(saddr));
}
__device__ __forceinline__ void cp_async16(uint32_t saddr, const void* gaddr) {
    asm volatile("cp.async.cg.shared.global [%0], [%1], 16;" :: "r"(saddr), "l"(gaddr));
}
__device__ __forceinline__ void cp_commit() { asm volatile("cp.async.commit_group;"); }
template <int N_> __device__ __forceinline__ void cp_wait() {
    asm volatile("cp.async.wait_group %0;" :: "n"(N_));
}
static __device__ __forceinline__ uint32_t smem_u32(const void* p) {
    uint32_t a;
    asm("{ .reg .u64 t; cvta.to.shared.u64 t, %1; cvt.u32.u64 %0, t; }" : "=r"(a) : "l"(p));
    return a;
}

__global__ __launch_bounds__(256, 2)
void gemm_f16_dual(const __half* __restrict__ A,
                   const __half* __restrict__ B1, const __half* __restrict__ B2,
                   __half* __restrict__ C1, __half* __restrict__ C2,
                   const float* __restrict__ a_s, const float* __restrict__ a_d,
                   int M, int N1, int N2, int K) {
    extern __shared__ __half hsm[];
    const uint32_t s0 = smem_u32(hsm);

    const int bnG = blockIdx.x * 128;
    const bool second = bnG >= N1;
    const __half* B = second ? B2 : B1;
    __half* C = second ? C2 : C1;
    const int bn = second ? bnG - N1 : bnG;
    const int Nc = second ? N2 : N1;
    const int H = N1 >> 8;

    const int bm = blockIdx.y * 128;
    const int t = threadIdx.x;
    const int w = t >> 5, lane = t & 31;
    const int wm = (w >> 1) * 32;
    const int wn = (w & 1) * 64;
    const int g = lane >> 2;
    const int r = lane & 3;

    const int sub = lane >> 3;
    const int frow = (sub & 1) * 8 + (lane & 7);
    const int fkof = (sub >> 1) * 8;

    float acc[2][8][4];
#pragma unroll
    for (int mi = 0; mi < 2; mi++)
#pragma unroll
        for (int ni = 0; ni < 8; ni++)
#pragma unroll
            for (int q = 0; q < 4; q++) acc[mi][ni][q] = 0.f;

    const int nIter = K / HBK;

    const int c0 = t, c1 = t + 256;
    const int r0 = c0 >> 2, kc0 = (c0 & 3) * 8;
    const int r1 = c1 >> 2, kc1 = (c1 & 3) * 8;
    const __half* gA0 = A + (size_t)min(bm + r0, M - 1) * K + kc0;
    const __half* gA1 = A + (size_t)min(bm + r1, M - 1) * K + kc1;
    const __half* gB0 = B + (size_t)(bn + r0) * K + kc0;
    const __half* gB1 = B + (size_t)(bn + r1) * K + kc1;
    const uint32_t sa0 = (uint32_t)(r0 * HSTRIDE + kc0) * 2;
    const uint32_t sa1 = (uint32_t)(r1 * HSTRIDE + kc1) * 2;

    auto load_stage = [&](int j) {
        const int s = j & 3;
        const int k0 = j * HBK;
        const uint32_t aS = s0 + s * HSTAGE_BYTES;
        const uint32_t bS = aS + 128 * HSTRIDE * 2;
        cp_async16(aS + sa0, gA0 + k0);
        cp_async16(aS + sa1, gA1 + k0);
        cp_async16(bS + sa0, gB0 + k0);
        cp_async16(bS + sa1, gB1 + k0);
        cp_commit();
    };

    load_stage(0);
    load_stage(1);
    load_stage(2);

    for (int j = 0; j < nIter; j++) {
        const int s = j & 3;
        if (j + 2 < nIter)      cp_wait<2>();
        else if (j + 1 < nIter) cp_wait<1>();
        else                    cp_wait<0>();
        __syncthreads();
        if (j + 3 < nIter) load_stage(j + 3);

        const uint32_t aS = s0 + s * HSTAGE_BYTES;
        const uint32_t bS = aS + 128 * HSTRIDE * 2;
#pragma unroll
        for (int ks = 0; ks < 2; ks++) {
            const int kb = ks * 16;
            uint32_t af[4], af2[4], bf[8][2];
            ldsm_x4(af, aS + ((wm + frow) * HSTRIDE + kb + fkof) * 2);
            ldsm_x4(af2, aS + ((wm + 16 + frow) * HSTRIDE + kb + fkof) * 2);
#pragma unroll
            for (int np = 0; np < 4; np++) {
                uint32_t rr[4];
                ldsm_x4(rr, bS + ((wn + np * 16 + frow) * HSTRIDE + kb + fkof) * 2);
                bf[2 * np + 0][0] = rr[0];
                bf[2 * np + 1][0] = rr[1];
                bf[2 * np + 0][1] = rr[2];
                bf[2 * np + 1][1] = rr[3];
            }
#pragma unroll
            for (int ni = 0; ni < 8; ni++) {
                mma_f16(acc[0][ni], af, bf[ni]);
                mma_f16(acc[1][ni], af2, bf[ni]);
            }
        }
    }

    // epilogue (fp16 both outputs)
#pragma unroll
    for (int mi = 0; mi < 2; mi++) {
        int row0 = bm + wm + mi * 16 + g;
        int row1 = row0 + 8;
#pragma unroll
        for (int ni = 0; ni < 8; ni++) {
            int col = bn + wn + ni * 8 + 2 * r;
            if (row0 < M)
                *reinterpret_cast<__half2*>(C + (size_t)row0 * Nc + col) =
                    __floats2half2_rn(acc[mi][ni][0], acc[mi][ni][1]);
            if (row1 < M)
                *reinterpret_cast<__half2*>(C + (size_t)row1 * Nc + col) =
                    __floats2half2_rn(acc[mi][ni][2], acc[mi][ni][3]);
        }
    }

    // alpha partials (first half only); slot = 2*(column-128-tile) + warp-n-half
    if (!second) {
        const int head = bnG >> 8;
        const int slot = ((bnG >> 7) & 1) * 2 + (wn >> 6);
        float av_s[16], av_d[16];
        const int base = head * 256 + (bnG & 255) + wn + 2 * r;
#pragma unroll
        for (int ni = 0; ni < 8; ni++) {
#pragma unroll
            for (int q = 0; q < 2; q++) {
                av_s[ni * 2 + q] = a_s[base + ni * 8 + q];
                av_d[ni * 2 + q] = a_d[base + ni * 8 + q];
            }
        }
        float ps[4], pd[4];
#pragma unroll
        for (int k = 0; k < 4; k++) { ps[k] = 0.f; pd[k] = 0.f; }
#pragma unroll
        for (int mi = 0; mi < 2; mi++) {
#pragma unroll
            for (int ni = 0; ni < 8; ni++) {
                ps[mi * 2 + 0] += acc[mi][ni][0] * av_s[ni * 2] + acc[mi][ni][1] * av_s[ni * 2 + 1];
                ps[mi * 2 + 1] += acc[mi][ni][2] * av_s[ni * 2] + acc[mi][ni][3] * av_s[ni * 2 + 1];
                pd[mi * 2 + 0] += acc[mi][ni][0] * av_d[ni * 2] + acc[mi][ni][1] * av_d[ni * 2 + 1];
                pd[mi * 2 + 1] += acc[mi][ni][2] * av_d[ni * 2] + acc[mi][ni][3] * av_d[ni * 2 + 1];
            }
        }
#pragma unroll
        for (int o = 1; o < 4; o <<= 1) {
#pragma unroll
            for (int k = 0; k < 4; k++) {
                ps[k] += __shfl_xor_sync(0xffffffffu, ps[k], o);
                pd[k] += __shfl_xor_sync(0xffffffffu, pd[k], o);
            }
        }
        if (r == 0) {
#pragma unroll
            for (int mi = 0; mi < 2; mi++) {
                int row0 = bm + wm + mi * 16 + g;
                int row1 = row0 + 8;
                if (row0 < M) {
                    g_asp[(row0 * H + head) * 4 + slot] = ps[mi * 2 + 0];
                    g_adp[(row0 * H + head) * 4 + slot] = pd[mi * 2 + 0];
                }
                if (row1 < M) {
                    g_asp[(row1 * H + head) * 4 + slot] = ps[mi * 2 + 1];
                    g_adp[(row1 * H + head) * 4 + slot] = pd[mi * 2 + 1];
                }
            }
        }
    }
}

__device__ __forceinline__ float lrelu(float x) { return x > 0.f ? x : 0.2f * x; }

// ---------------- fused segment-softmax + aggregation + epilogue ----------------
template <int H, bool MEAN, bool APPLY_ELU, typename OT>
__global__ void gat_agg(const float* __restrict__ bgat, const float* __restrict__ lb,
                        OT* __restrict__ out) {
    int n = blockIdx.x;
    int t = threadIdx.x;
    int start = g_rowptr[n];
    int deg = g_rowptr[n + 1] - start;

    __shared__ float s_m[H], s_dinv[H];
    int w = t >> 5, lane = t & 31;
    if (w < H) {
        float ad = g_ad[n * H + w];
        float mx = -1e30f;
        for (int j = lane; j < deg; j += 32)
            mx = fmaxf(mx, lrelu(g_as[g_col[start + j] * H + w] + ad));
#pragma unroll
        for (int o = 16; o; o >>= 1) mx = fmaxf(mx, __shfl_xor_sync(0xffffffffu, mx, o));
        float sum = 0.f;
        for (int j = lane; j < deg; j += 32)
            sum += __expf(lrelu(g_as[g_col[start + j] * H + w] + ad) - mx);
#pragma unroll
        for (int o = 16; o; o >>= 1) sum += __shfl_xor_sync(0xffffffffu, sum, o);
        if (lane == 0) { s_m[w] = mx; s_dinv[w] = 1.f / (sum + 1e-16f); }
    }
    __syncthreads();

    const int CH = 32;
    __shared__ float s_coef[CH][H];
    __shared__ int   s_src[CH];
    const int hA = t >> 6;
    const int hB = 4 + (t >> 7);

    float2 accA0 = make_float2(0.f, 0.f);
    float2 accA1 = make_float2(0.f, 0.f);
    float2 accB  = make_float2(0.f, 0.f);

    for (int cs = 0; cs < deg; cs += CH) {
        int cnt = min(CH, deg - cs);
        if (t < cnt) s_src[t] = g_col[start + cs + t];
        for (int idx = t; idx < cnt * H; idx += 256) {
            int j = idx / H, h = idx - j * H;
            int s = g_col[start + cs + j];
            float ee = lrelu(g_as[s * H + h] + g_ad[n * H + h]);
            s_coef[j][h] = __expf(ee - s_m[h]) * s_dinv[h];
        }
        __syncthreads();
        for (int j = 0; j < cnt; j++) {
            const __half* row = g_h + (size_t)s_src[j] * (H * 256);
            uint2 va = *reinterpret_cast<const uint2*>(row + 4 * t);
            float cA = s_coef[j][hA];
            float2 f0 = __half22float2(*reinterpret_cast<__half2*>(&va.x));
            float2 f1 = __half22float2(*reinterpret_cast<__half2*>(&va.y));
            accA0.x = fmaf(f0.x, cA, accA0.x);
            accA0.y = fmaf(f0.y, cA, accA0.y);
            accA1.x = fmaf(f1.x, cA, accA1.x);
            accA1.y = fmaf(f1.y, cA, accA1.y);
            if (H == 6) {
                __half2 vb = *reinterpret_cast<const __half2*>(row + 1024 + 2 * t);
                float cB = s_coef[j][hB];
                float2 fb = __half22float2(vb);
                accB.x = fmaf(fb.x, cB, accB.x);
                accB.y = fmaf(fb.y, cB, accB.y);
            }
        }
        __syncthreads();
    }

    if (MEAN) {
        __shared__ float s_sum[256];
        s_sum[t] = 0.f;
        __syncthreads();
        int cA = (4 * t) & 255;
        atomicAdd(&s_sum[cA + 0], accA0.x);
        atomicAdd(&s_sum[cA + 1], accA0.y);
        atomicAdd(&s_sum[cA + 2], accA1.x);
        atomicAdd(&s_sum[cA + 3], accA1.y);
        int cB = (2 * t) & 255;
        atomicAdd(&s_sum[cB + 0], accB.x);
        atomicAdd(&s_sum[cB + 1], accB.y);
        __syncthreads();
        float ln = __half2float(g_linh[(size_t)n * 256 + t]);
        float v = s_sum[t] * (1.f / (float)H) + bgat[t] + ln + lb[t];
        reinterpret_cast<float*>(out)[(size_t)n * 256 + t] = v;
    } else {
        int c = 4 * t;
        float4 bg = *reinterpret_cast<const float4*>(bgat + c);
        float4 lb4 = *reinterpret_cast<const float4*>(lb + c);
        uint2 lv = *reinterpret_cast<const uint2*>(g_linh + (size_t)n * 1024 + c);
        float2 l0 = __half22float2(*reinterpret_cast<__half2*>(&lv.x));
        float2 l1 = __half22float2(*reinterpret_cast<__half2*>(&lv.y));
        float v0 = accA0.x + bg.x + l0.x + lb4.x;
        float v1 = accA0.y + bg.y + l0.y + lb4.y;
        float v2 = accA1.x + bg.z + l1.x + lb4.z;
        float v3 = accA1.y + bg.w + l1.y + lb4.w;
        if (APPLY_ELU) {
            v0 = v0 > 0.f ? v0 : (__expf(v0) - 1.f);
            v1 = v1 > 0.f ? v1 : (__expf(v1) - 1.f);
            v2 = v2 > 0.f ? v2 : (__expf(v2) - 1.f);
            v3 = v3 > 0.f ? v3 : (__expf(v3) - 1.f);
        }
        uint2 o;
        __half2 ha = __floats2half2_rn(v0, v1);
        __half2 hb = __floats2half2_rn(v2, v3);
        o.x = *reinterpret_cast<uint32_t*>(&ha);
        o.y = *reinterpret_cast<uint32_t*>(&hb);
        *reinterpret_cast<uint2*>(reinterpret_cast<__half*>(out) + (size_t)n * 1024 + c) = o;
    }
}

// ---------------- host launcher ----------------
static inline void run_gemm_dual_tc(const __half* A, const __half* B1, const __half* B2,
                                    __half* C1, __half* C2,
                                    const float* a_s, const float* a_d,
                                    int M, int N1, int N2, int K) {
    dim3 grid((N1 + N2) / 128, (M + 127) / 128);
    gemm_f16_dual<<<grid, 256, HSMEM_BYTES>>>(A, B1, B2, C1, C2, a_s, a_d, M, N1, N2, K);
}

extern "C" void kernel_launch(void* const* d_in, const int* in_sizes, int n_in,
                              void* d_out, int out_size) {
    const float* x   = (const float*)d_in[0];
    const int*   ei  = (const int*)d_in[1];
    const float* W1  = (const float*)d_in[2];
    const float* a1s = (const float*)d_in[3];
    const float* a1d = (const float*)d_in[4];
    const float* b1  = (const float*)d_in[5];
    const float* lw1 = (const float*)d_in[6];
    const float* lb1 = (const float*)d_in[7];
    const float* W2  = (const float*)d_in[8];
    const float* a2s = (const float*)d_in[9];
    const float* a2d = (const float*)d_in[10];
    const float* b2  = (const float*)d_in[11];
    const float* lw2 = (const float*)d_in[12];
    const float* lb2 = (const float*)d_in[13];
    const float* W3  = (const float*)d_in[14];
    const float* a3s = (const float*)d_in[15];
    const float* a3d = (const float*)d_in[16];
    const float* b3  = (const float*)d_in[17];
    const float* lw3 = (const float*)d_in[18];
    const float* lb3 = (const float*)d_in[19];
    float* out = (float*)d_out;

    cudaFuncSetAttribute(gemm_f16_dual, cudaFuncAttributeMaxDynamicSharedMemorySize,
                         HSMEM_BYTES);

    void *p_h, *p_lin, *p_x1h, *p_x2h;
    cudaGetSymbolAddress(&p_h, g_h);
    cudaGetSymbolAddress(&p_lin, g_linh);
    cudaGetSymbolAddress(&p_x1h, g_x1h);
    cudaGetSymbolAddress(&p_x2h, g_x2h);
    __half* h    = (__half*)p_h;
    __half* lin  = (__half*)p_lin;
    __half* x1h  = (__half*)p_x1h;
    __half* x2h  = (__half*)p_x2h;

    void *p_w2h, *p_lw2h, *p_w3h, *p_lw3h;
    cudaGetSymbolAddress(&p_w2h, g_w2h);
    cudaGetSymbolAddress(&p_lw2h, g_lw2h);
    cudaGetSymbolAddress(&p_w3h, g_w3h);
    cudaGetSymbolAddress(&p_lw3h, g_lw3h);
    __half* w2h  = (__half*)p_w2h;
    __half* lw2h = (__half*)p_lw2h;
    __half* w3h  = (__half*)p_w3h;
    __half* lw3h = (__half*)p_lw3h;

    void *p_cnt, *p_fill;
    cudaGetSymbolAddress(&p_cnt, g_cnt);
    cudaGetSymbolAddress(&p_fill, g_fill);

    // zero counters
    cudaMemsetAsync(p_cnt, 0, N_NODES * sizeof(int));
    cudaMemsetAsync(p_fill, 0, N_NODES * sizeof(int));

    // fused: weight conversion + edge counting (independent work, one launch)
    k_f2h_count<<<F2H_BLOCKS + CNT_BLOCKS, 256>>>(W2, lw2, W3, lw3, ei);
    k_scan_one<<<1, 1024>>>();

    // ---- layer 1 GEMM (+ fused CSR scatter in tail blocks) ----
    {
        const int mtiles = (N_NODES + 127) / 128;                 // 79
        const int scat_rows = (CNT_BLOCKS + 31) / 32;             // 21
        dim3 grid((1024 + 1024) / 64, mtiles + scat_rows);
        sgemm_dual<<<grid, 256>>>(x, W1, lw1, h, lin, a1s, a1d, ei,
                                  N_NODES, 1024, 1024, 14);
    }
    k_alpha_fix<<<(N_NODES * 4 + 255) / 256, 256>>>(N_NODES * 4);
    gat_agg<4, false, true, __half><<<N_NODES, 256>>>(b1, lb1, x1h);

    // ---- layer 2: 1024 -> 4x256, concat, +skip, ELU ----
    run_gemm_dual_tc(x1h, w2h, lw2h, h, lin, a2s, a2d, N_NODES, 1024, 1024, 1024);
    k_alpha_fix<<<(N_NODES * 4 + 255) / 256, 256>>>(N_NODES * 4);
    gat_agg<4, false, true, __half><<<N_NODES, 256>>>(b2, lb2, x2h);

    // ---- layer 3: 1024 -> mean of 6x256, +skip, no ELU ----
    run_gemm_dual_tc(x2h, w3h, lw3h, h, lin, a3s, a3d, N_NODES, 1536, 256, 1024);
    k_alpha_fix<<<(N_NODES * 6 + 255) / 256, 256>>>(N_NODES * 6);
    gat_agg<6, true, false, float><<<N_NODES, 256>>>(b3, lb3, out);
}

// round 14
// speedup vs baseline: 1.0705x; 1.0351x over previous
#include <cuda_runtime.h>
#include <cuda_fp16.h>
#include <math.h>
#include <stdint.h>

#define N_NODES 10000
#define N_EDGES 160000
#define ET (N_EDGES + N_NODES)

// ---------------- scratch (static __device__, no allocations) ----------------
__device__ __half g_h[(size_t)N_NODES * 1536];     // GAT linear output, fp16
__device__ __half g_linh[(size_t)N_NODES * 1024];  // skip-linear output, fp16
__device__ __half g_x1h[(size_t)N_NODES * 1024];
__device__ __half g_x2h[(size_t)N_NODES * 1024];
__device__ __half g_w2h[1024 * 1024];
__device__ __half g_lw2h[1024 * 1024];
__device__ __half g_w3h[1536 * 1024];
__device__ __half g_lw3h[256 * 1024];
__device__ float  g_asp[N_NODES * 6 * 4];   // alpha_src partials (4 slots, single-writer)
__device__ float  g_adp[N_NODES * 6 * 4];   // alpha_dst partials
__device__ int    g_rowptr[N_NODES + 1];
__device__ int    g_cnt[N_NODES];
__device__ int    g_fill[N_NODES];
__device__ int    g_col[ET];

// ---------------- single-block scan: 1024 threads x 10 elements ----------------
__global__ void k_scan_one() {
    const int t = threadIdx.x;
    const int lane = t & 31, w = t >> 5;
    const int base = t * 10;
    int vals[10];
    int s = 0;
#pragma unroll
    for (int k = 0; k < 10; k++) {
        int i = base + k;
        int v = (i < N_NODES) ? g_cnt[i] : 0;
        s += v;
        vals[k] = s;
    }
    int x = s;
#pragma unroll
    for (int o = 1; o < 32; o <<= 1) {
        int y = __shfl_up_sync(0xffffffffu, x, o);
        if (lane >= o) x += y;
    }
    __shared__ int ws[32];
    if (lane == 31) ws[w] = x;
    __syncthreads();
    if (w == 0) {
        int v = ws[lane];
#pragma unroll
        for (int o = 1; o < 32; o <<= 1) {
            int y = __shfl_up_sync(0xffffffffu, v, o);
            if (lane >= o) v += y;
        }
        ws[lane] = v;
    }
    __syncthreads();
    int warp_excl = (w == 0) ? 0 : ws[w - 1];
    int thr_excl = warp_excl + (x - s);
#pragma unroll
    for (int k = 0; k < 10; k++) {
        int i = base + k;
        if (i < N_NODES) g_rowptr[i + 1] = thr_excl + vals[k];
    }
    if (t == 0) g_rowptr[0] = 0;
}

// ---------------- fused fp32->fp16 weight conversion + edge counting ----------
#define S_W2  (1024 * 1024)
#define S_LW2 (1024 * 1024)
#define S_W3  (1536 * 1024)
#define S_LW3 (256 * 1024)
#define F2H_TOTAL4 ((S_W2 + S_LW2 + S_W3 + S_LW3) / 4)
#define F2H_BLOCKS ((F2H_TOTAL4 + 255) / 256)      // 3840
#define CNT_BLOCKS ((ET + 255) / 256)              // 665

__global__ void k_f2h_count(const float* __restrict__ W2, const float* __restrict__ lw2,
                            const float* __restrict__ W3, const float* __restrict__ lw3,
                            const int* __restrict__ ei) {
    if (blockIdx.x >= F2H_BLOCKS) {
        int i = (blockIdx.x - F2H_BLOCKS) * blockDim.x + threadIdx.x;
        if (i < ET) {
            int d = (i < N_EDGES) ? ei[N_EDGES + i] : (i - N_EDGES);
            atomicAdd(&g_cnt[d], 1);
        }
        return;
    }
    int i = blockIdx.x * blockDim.x + threadIdx.x;
    if (i >= F2H_TOTAL4) return;
    const float* src;
    __half* dst;
    int off;
    if (i < S_W2 / 4)                      { src = W2;  dst = g_w2h;  off = i; }
    else if (i < (S_W2 + S_LW2) / 4)       { src = lw2; dst = g_lw2h; off = i - S_W2 / 4; }
    else if (i < (S_W2 + S_LW2 + S_W3) / 4){ src = W3;  dst = g_w3h;  off = i - (S_W2 + S_LW2) / 4; }
    else                                   { src = lw3; dst = g_lw3h; off = i - (S_W2 + S_LW2 + S_W3) / 4; }
    float4 v = *reinterpret_cast<const float4*>(src + 4 * off);
    uint2 o;
    __half2 a = __floats2half2_rn(v.x, v.y);
    __half2 b = __floats2half2_rn(v.z, v.w);
    o.x = *reinterpret_cast<uint32_t*>(&a);
    o.y = *reinterpret_cast<uint32_t*>(&b);
    *reinterpret_cast<uint2*>(dst + 4 * off) = o;
}

// -------- scalar SGEMM dual-output (layer 1, K=14) + fused edge scatter --------
__global__ void sgemm_dual(const float* __restrict__ A,
                           const float* __restrict__ B1, const float* __restrict__ B2,
                           __half* __restrict__ C1, __half* __restrict__ C2,
                           const float* __restrict__ a_s, const float* __restrict__ a_d,
                           const int* __restrict__ ei,
                           int M, int N1, int N2, int K) {
    const int BM = 128, BN = 64, BK = 16;
    const int mtiles = (M + BM - 1) / BM;
    if ((int)blockIdx.y >= mtiles) {
        int sb = (blockIdx.y - mtiles) * gridDim.x + blockIdx.x;
        int i = sb * 256 + threadIdx.x;
        if (i < ET) {
            int s, d;
            if (i < N_EDGES) { s = ei[i]; d = ei[N_EDGES + i]; }
            else             { s = d = i - N_EDGES; }
            int pos = g_rowptr[d] + atomicAdd(&g_fill[d], 1);
            g_col[pos] = s;
        }
        return;
    }

    __shared__ float As[BK][BM + 4];
    __shared__ float Bs[BK][BN + 4];
    int bnG = blockIdx.x * BN;
    bool second = bnG >= N1;
    const float* B = second ? B2 : B1;
    __half* C = second ? C2 : C1;
    int bn = second ? bnG - N1 : bnG;
    int Nc = second ? N2 : N1;
    const int H = N1 >> 8;

    int bm = blockIdx.y * BM;
    int t = threadIdx.x;
    int tx = t & 15, ty = t >> 4;
    float acc[8][4];
#pragma unroll
    for (int i = 0; i < 8; i++)
#pragma unroll
        for (int j = 0; j < 4; j++) acc[i][j] = 0.f;
    for (int k0 = 0; k0 < K; k0 += BK) {
#pragma unroll
        for (int i = 0; i < 8; i++) {
            int idx = t + i * 256;
            int r = idx >> 4, kk = idx & 15;
            int gr = bm + r, gk = k0 + kk;
            As[kk][r] = (gr < M && gk < K) ? A[(size_t)gr * K + gk] : 0.f;
        }
#pragma unroll
        for (int i = 0; i < 4; i++) {
            int idx = t + i * 256;
            int r = idx >> 4, kk = idx & 15;
            int gr = bn + r, gk = k0 + kk;
            Bs[kk][r] = (gr < Nc && gk < K) ? B[(size_t)gr * K + gk] : 0.f;
        }
        __syncthreads();
#pragma unroll
        for (int kk = 0; kk < BK; kk++) {
            float a[8], b[4];
#pragma unroll
            for (int i = 0; i < 8; i++) a[i] = As[kk][ty * 8 + i];
#pragma unroll
            for (int j = 0; j < 4; j++) b[j] = Bs[kk][tx * 4 + j];
#pragma unroll
            for (int i = 0; i < 8; i++)
#pragma unroll
                for (int j = 0; j < 4; j++) acc[i][j] = fmaf(a[i], b[j], acc[i][j]);
        }
        __syncthreads();
    }
#pragma unroll
    for (int i = 0; i < 8; i++) {
        int r = bm + ty * 8 + i;
        if (r >= M) continue;
        int c = bn + tx * 4;
        __half2 h0 = __floats2half2_rn(acc[i][0], acc[i][1]);
        __half2 h1 = __floats2half2_rn(acc[i][2], acc[i][3]);
        uint2 o;
        o.x = *reinterpret_cast<uint32_t*>(&h0);
        o.y = *reinterpret_cast<uint32_t*>(&h1);
        *reinterpret_cast<uint2*>(C + (size_t)r * Nc + c) = o;
    }

    if (!second) {
        int head = bnG >> 8;
        int slot = (bnG >> 6) & 3;
        float av_s[4], av_d[4];
        int base = (bnG & 255) + tx * 4;
#pragma unroll
        for (int j = 0; j < 4; j++) {
            av_s[j] = a_s[head * 256 + base + j];
            av_d[j] = a_d[head * 256 + base + j];
        }
#pragma unroll
        for (int i = 0; i < 8; i++) {
            float ps = acc[i][0] * av_s[0] + acc[i][1] * av_s[1] +
                       acc[i][2] * av_s[2] + acc[i][3] * av_s[3];
            float pd = acc[i][0] * av_d[0] + acc[i][1] * av_d[1] +
                       acc[i][2] * av_d[2] + acc[i][3] * av_d[3];
#pragma unroll
            for (int o = 1; o < 16; o <<= 1) {
                ps += __shfl_xor_sync(0xffffffffu, ps, o);
                pd += __shfl_xor_sync(0xffffffffu, pd, o);
            }
            int r = bm + ty * 8 + i;
            if (tx == 0 && r < M) {
                g_asp[(r * H + head) * 4 + slot] = ps;
                g_adp[(r * H + head) * 4 + slot] = pd;
            }
        }
    }
}

// ====== fp16 tensor-core dual GEMM (mma.sync m16n8k16): [C1|C2] = A*[B1|B2]^T ======
#define HBK 32
#define HSTRIDE 40
#define HSTAGE_BYTES (2 * 128 * HSTRIDE * 2)
#define HSMEM_BYTES  (4 * HSTAGE_BYTES)

__device__ __forceinline__ void mma_f16(float c[4], const uint32_t a[4], const uint32_t b[2]) {
    asm volatile(
        "mma.sync.aligned.m16n8k16.row.col.f32.f16.f16.f32 "
        "{%0,%1,%2,%3}, {%4,%5,%6,%7}, {%8,%9}, {%0,%1,%2,%3};"
        : "+f"(c[0]), "+f"(c[1]), "+f"(c[2]), "+f"(c[3])
        : "r"(a[0]), "r"(a[1]), "r"(a[2]), "r"(a[3]), "r"(b[0]), "r"(b[1]));
}
__device__ __forceinline__ void ldsm_x4(uint32_t r[4], uint32_t saddr) {
    asm volatile("ldmatrix.sync.aligned.m8n8.x4.shared.b16 {%0,%1,%2,%3}, [%4];"
                 : "=r"(r[0]), "=r"(r[1]), "=r"(r[2]), "=r"(r[3]) : "r"(saddr));
}
__device__ __forceinline__ void cp_async16(uint32_t saddr, const void* gaddr) {
    asm volatile("cp.async.cg.shared.global [%0], [%1], 16;" :: "r"(saddr), "l"(gaddr));
}
__device__ __forceinline__ void cp_commit() { asm volatile("cp.async.commit_group;"); }
template <int N_> __device__ __forceinline__ void cp_wait() {
    asm volatile("cp.async.wait_group %0;" :: "n"(N_));
}
static __device__ __forceinline__ uint32_t smem_u32(const void* p) {
    uint32_t a;
    asm("{ .reg .u64 t; cvta.to.shared.u64 t, %1; cvt.u32.u64 %0, t; }" : "=r"(a) : "l"(p));
    return a;
}

__global__ __launch_bounds__(256, 2)
void gemm_f16_dual(const __half* __restrict__ A,
                   const __half* __restrict__ B1, const __half* __restrict__ B2,
                   __half* __restrict__ C1, __half* __restrict__ C2,
                   const float* __restrict__ a_s, const float* __restrict__ a_d,
                   int M, int N1, int N2, int K) {
    extern __shared__ __half hsm[];
    const uint32_t s0 = smem_u32(hsm);

    const int bnG = blockIdx.x * 128;
    const bool second = bnG >= N1;
    const __half* B = second ? B2 : B1;
    __half* C = second ? C2 : C1;
    const int bn = second ? bnG - N1 : bnG;
    const int Nc = second ? N2 : N1;
    const int H = N1 >> 8;

    const int bm = blockIdx.y * 128;
    const int t = threadIdx.x;
    const int w = t >> 5, lane = t & 31;
    const int wm = (w >> 1) * 32;
    const int wn = (w & 1) * 64;
    const int g = lane >> 2;
    const int r = lane & 3;

    const int sub = lane >> 3;
    const int frow = (sub & 1) * 8 + (lane & 7);
    const int fkof = (sub >> 1) * 8;

    float acc[2][8][4];
#pragma unroll
    for (int mi = 0; mi < 2; mi++)
#pragma unroll
        for (int ni = 0; ni < 8; ni++)
#pragma unroll
            for (int q = 0; q < 4; q++) acc[mi][ni][q] = 0.f;

    const int nIter = K / HBK;

    const int c0 = t, c1 = t + 256;
    const int r0 = c0 >> 2, kc0 = (c0 & 3) * 8;
    const int r1 = c1 >> 2, kc1 = (c1 & 3) * 8;
    const __half* gA0 = A + (size_t)min(bm + r0, M - 1) * K + kc0;
    const __half* gA1 = A + (size_t)min(bm + r1, M - 1) * K + kc1;
    const __half* gB0 = B + (size_t)(bn + r0) * K + kc0;
    const __half* gB1 = B + (size_t)(bn + r1) * K + kc1;
    const uint32_t sa0 = (uint32_t)(r0 * HSTRIDE + kc0) * 2;
    const uint32_t sa1 = (uint32_t)(r1 * HSTRIDE + kc1) * 2;

    auto load_stage = [&](int j) {
        const int s = j & 3;
        const int k0 = j * HBK;
        const uint32_t aS = s0 + s * HSTAGE_BYTES;
        const uint32_t bS = aS + 128 * HSTRIDE * 2;
        cp_async16(aS + sa0, gA0 + k0);
        cp_async16(aS + sa1, gA1 + k0);
        cp_async16(bS + sa0, gB0 + k0);
        cp_async16(bS + sa1, gB1 + k0);
        cp_commit();
    };

    load_stage(0);
    load_stage(1);
    load_stage(2);

    for (int j = 0; j < nIter; j++) {
        const int s = j & 3;
        if (j + 2 < nIter)      cp_wait<2>();
        else if (j + 1 < nIter) cp_wait<1>();
        else                    cp_wait<0>();
        __syncthreads();
        if (j + 3 < nIter) load_stage(j + 3);

        const uint32_t aS = s0 + s * HSTAGE_BYTES;
        const uint32_t bS = aS + 128 * HSTRIDE * 2;
#pragma unroll
        for (int ks = 0; ks < 2; ks++) {
            const int kb = ks * 16;
            uint32_t af[4], af2[4], bf[8][2];
            ldsm_x4(af, aS + ((wm + frow) * HSTRIDE + kb + fkof) * 2);
            ldsm_x4(af2, aS + ((wm + 16 + frow) * HSTRIDE + kb + fkof) * 2);
#pragma unroll
            for (int np = 0; np < 4; np++) {
                uint32_t rr[4];
                ldsm_x4(rr, bS + ((wn + np * 16 + frow) * HSTRIDE + kb + fkof) * 2);
                bf[2 * np + 0][0] = rr[0];
                bf[2 * np + 1][0] = rr[1];
                bf[2 * np + 0][1] = rr[2];
                bf[2 * np + 1][1] = rr[3];
            }
#pragma unroll
            for (int ni = 0; ni < 8; ni++) {
                mma_f16(acc[0][ni], af, bf[ni]);
                mma_f16(acc[1][ni], af2, bf[ni]);
            }
        }
    }

#pragma unroll
    for (int mi = 0; mi < 2; mi++) {
        int row0 = bm + wm + mi * 16 + g;
        int row1 = row0 + 8;
#pragma unroll
        for (int ni = 0; ni < 8; ni++) {
            int col = bn + wn + ni * 8 + 2 * r;
            if (row0 < M)
                *reinterpret_cast<__half2*>(C + (size_t)row0 * Nc + col) =
                    __floats2half2_rn(acc[mi][ni][0], acc[mi][ni][1]);
            if (row1 < M)
                *reinterpret_cast<__half2*>(C + (size_t)row1 * Nc + col) =
                    __floats2half2_rn(acc[mi][ni][2], acc[mi][ni][3]);
        }
    }

    if (!second) {
        const int head = bnG >> 8;
        const int slot = ((bnG >> 7) & 1) * 2 + (wn >> 6);
        float av_s[16], av_d[16];
        const int base = head * 256 + (bnG & 255) + wn + 2 * r;
#pragma unroll
        for (int ni = 0; ni < 8; ni++) {
#pragma unroll
            for (int q = 0; q < 2; q++) {
                av_s[ni * 2 + q] = a_s[base + ni * 8 + q];
                av_d[ni * 2 + q] = a_d[base + ni * 8 + q];
            }
        }
        float ps[4], pd[4];
#pragma unroll
        for (int k = 0; k < 4; k++) { ps[k] = 0.f; pd[k] = 0.f; }
#pragma unroll
        for (int mi = 0; mi < 2; mi++) {
#pragma unroll
            for (int ni = 0; ni < 8; ni++) {
                ps[mi * 2 + 0] += acc[mi][ni][0] * av_s[ni * 2] + acc[mi][ni][1] * av_s[ni * 2 + 1];
                ps[mi * 2 + 1] += acc[mi][ni][2] * av_s[ni * 2] + acc[mi][ni][3] * av_s[ni * 2 + 1];
                pd[mi * 2 + 0] += acc[mi][ni][0] * av_d[ni * 2] + acc[mi][ni][1] * av_d[ni * 2 + 1];
                pd[mi * 2 + 1] += acc[mi][ni][2] * av_d[ni * 2] + acc[mi][ni][3] * av_d[ni * 2 + 1];
            }
        }
#pragma unroll
        for (int o = 1; o < 4; o <<= 1) {
#pragma unroll
            for (int k = 0; k < 4; k++) {
                ps[k] += __shfl_xor_sync(0xffffffffu, ps[k], o);
                pd[k] += __shfl_xor_sync(0xffffffffu, pd[k], o);
            }
        }
        if (r == 0) {
#pragma unroll
            for (int mi = 0; mi < 2; mi++) {
                int row0 = bm + wm + mi * 16 + g;
                int row1 = row0 + 8;
                if (row0 < M) {
                    g_asp[(row0 * H + head) * 4 + slot] = ps[mi * 2 + 0];
                    g_adp[(row0 * H + head) * 4 + slot] = pd[mi * 2 + 0];
                }
                if (row1 < M) {
                    g_asp[(row1 * H + head) * 4 + slot] = ps[mi * 2 + 1];
                    g_adp[(row1 * H + head) * 4 + slot] = pd[mi * 2 + 1];
                }
            }
        }
    }
}

__device__ __forceinline__ float lrelu(float x) { return x > 0.f ? x : 0.2f * x; }

__device__ __forceinline__ float sum4(const float* p) {
    float4 v = *reinterpret_cast<const float4*>(p);
    return (v.x + v.y) + (v.z + v.w);
}

// ---------------- fused segment-softmax + aggregation + epilogue ----------------
// Reads alpha partials directly (no fixup kernel). Fast path for deg <= 32.
template <int H, bool MEAN, bool APPLY_ELU, typename OT>
__global__ void gat_agg(const float* __restrict__ bgat, const float* __restrict__ lb,
                        OT* __restrict__ out) {
    int n = blockIdx.x;
    int t = threadIdx.x;
    int start = g_rowptr[n];
    int deg = g_rowptr[n + 1] - start;
    int w = t >> 5, lane = t & 31;

    const int CH = 64;
    __shared__ float s_m[H], s_dinv[H], s_adn[H];
    __shared__ float s_coef[CH][H];
    __shared__ int   s_src[CH];

    if (t < H) s_adn[t] = sum4(g_adp + 4 * (n * H + t));
    __syncthreads();

    const int hA = t >> 6;                 // head of channels 4t..4t+3
    const int hB = 4 + (t >> 7);           // head of channels 1024+2t (H==6)
    float2 accA0 = make_float2(0.f, 0.f);
    float2 accA1 = make_float2(0.f, 0.f);
    float2 accB  = make_float2(0.f, 0.f);

    if (deg <= 32) {
        // fast path: one alpha read per (edge, head); coef straight to smem
        if (w < H) {
            float ad = s_adn[w];
            float val = -1e30f;
            if (lane < deg) {
                int s = g_col[start + lane];
                val = lrelu(sum4(g_asp + 4 * (s * H + w)) + ad);
            }
            float mx = val;
#pragma unroll
            for (int o = 16; o; o >>= 1) mx = fmaxf(mx, __shfl_xor_sync(0xffffffffu, mx, o));
            float e = (lane < deg) ? __expf(val - mx) : 0.f;
            float sum = e;
#pragma unroll
            for (int o = 16; o; o >>= 1) sum += __shfl_xor_sync(0xffffffffu, sum, o);
            if (lane < deg) s_coef[lane][w] = e / (sum + 1e-16f);
        }
        if (t < deg) s_src[t] = g_col[start + t];
        __syncthreads();
        for (int j = 0; j < deg; j++) {
            const __half* row = g_h + (size_t)s_src[j] * (H * 256);
            uint2 va = *reinterpret_cast<const uint2*>(row + 4 * t);
            float cA = s_coef[j][hA];
            float2 f0 = __half22float2(*reinterpret_cast<__half2*>(&va.x));
            float2 f1 = __half22float2(*reinterpret_cast<__half2*>(&va.y));
            accA0.x = fmaf(f0.x, cA, accA0.x);
            accA0.y = fmaf(f0.y, cA, accA0.y);
            accA1.x = fmaf(f1.x, cA, accA1.x);
            accA1.y = fmaf(f1.y, cA, accA1.y);
            if (H == 6) {
                __half2 vb = *reinterpret_cast<const __half2*>(row + 1024 + 2 * t);
                float cB = s_coef[j][hB];
                float2 fb = __half22float2(vb);
                accB.x = fmaf(fb.x, cB, accB.x);
                accB.y = fmaf(fb.y, cB, accB.y);
            }
        }
    } else {
        // slow path: chunked two-pass softmax
        if (w < H) {
            float ad = s_adn[w];
            float mx = -1e30f;
            for (int j = lane; j < deg; j += 32)
                mx = fmaxf(mx, lrelu(sum4(g_asp + 4 * (g_col[start + j] * H + w)) + ad));
#pragma unroll
            for (int o = 16; o; o >>= 1) mx = fmaxf(mx, __shfl_xor_sync(0xffffffffu, mx, o));
            float sum = 0.f;
            for (int j = lane; j < deg; j += 32)
                sum += __expf(lrelu(sum4(g_asp + 4 * (g_col[start + j] * H + w)) + ad) - mx);
#pragma unroll
            for (int o = 16; o; o >>= 1) sum += __shfl_xor_sync(0xffffffffu, sum, o);
            if (lane == 0) { s_m[w] = mx; s_dinv[w] = 1.f / (sum + 1e-16f); }
        }
        __syncthreads();
        for (int cs = 0; cs < deg; cs += CH) {
            int cnt = min(CH, deg - cs);
            if (t < cnt) s_src[t] = g_col[start + cs + t];
            for (int idx = t; idx < cnt * H; idx += 256) {
                int j = idx / H, h = idx - j * H;
                int s = g_col[start + cs + j];
                float ee = lrelu(sum4(g_asp + 4 * (s * H + h)) + s_adn[h]);
                s_coef[j][h] = __expf(ee - s_m[h]) * s_dinv[h];
            }
            __syncthreads();
            for (int j = 0; j < cnt; j++) {
                const __half* row = g_h + (size_t)s_src[j] * (H * 256);
                uint2 va = *reinterpret_cast<const uint2*>(row + 4 * t);
                float cA = s_coef[j][hA];
                float2 f0 = __half22float2(*reinterpret_cast<__half2*>(&va.x));
                float2 f1 = __half22float2(*reinterpret_cast<__half2*>(&va.y));
                accA0.x = fmaf(f0.x, cA, accA0.x);
                accA0.y = fmaf(f0.y, cA, accA0.y);
                accA1.x = fmaf(f1.x, cA, accA1.x);
                accA1.y = fmaf(f1.y, cA, accA1.y);
                if (H == 6) {
                    __half2 vb = *reinterpret_cast<const __half2*>(row + 1024 + 2 * t);
                    float cB = s_coef[j][hB];
                    float2 fb = __half22float2(vb);
                    accB.x = fmaf(fb.x, cB, accB.x);
                    accB.y = fmaf(fb.y, cB, accB.y);
                }
            }
            __syncthreads();
        }
    }

    if (MEAN) {
        __shared__ float s_sum[256];
        s_sum[t] = 0.f;
        __syncthreads();
        int cA = (4 * t) & 255;
        atomicAdd(&s_sum[cA + 0], accA0.x);
        atomicAdd(&s_sum[cA + 1], accA0.y);
        atomicAdd(&s_sum[cA + 2], accA1.x);
        atomicAdd(&s_sum[cA + 3], accA1.y);
        int cB = (2 * t) & 255;
        atomicAdd(&s_sum[cB + 0], accB.x);
        atomicAdd(&s_sum[cB + 1], accB.y);
        __syncthreads();
        float ln = __half2float(g_linh[(size_t)n * 256 + t]);
        float v = s_sum[t] * (1.f / (float)H) + bgat[t] + ln + lb[t];
        reinterpret_cast<float*>(out)[(size_t)n * 256 + t] = v;
    } else {
        int c = 4 * t;
        float4 bg = *reinterpret_cast<const float4*>(bgat + c);
        float4 lb4 = *reinterpret_cast<const float4*>(lb + c);
        uint2 lv = *reinterpret_cast<const uint2*>(g_linh + (size_t)n * 1024 + c);
        float2 l0 = __half22float2(*reinterpret_cast<__half2*>(&lv.x));
        float2 l1 = __half22float2(*reinterpret_cast<__half2*>(&lv.y));
        float v0 = accA0.x + bg.x + l0.x + lb4.x;
        float v1 = accA0.y + bg.y + l0.y + lb4.y;
        float v2 = accA1.x + bg.z + l1.x + lb4.z;
        float v3 = accA1.y + bg.w + l1.y + lb4.w;
        if (APPLY_ELU) {
            v0 = v0 > 0.f ? v0 : (__expf(v0) - 1.f);
            v1 = v1 > 0.f ? v1 : (__expf(v1) - 1.f);
            v2 = v2 > 0.f ? v2 : (__expf(v2) - 1.f);
            v3 = v3 > 0.f ? v3 : (__expf(v3) - 1.f);
        }
        uint2 o;
        __half2 ha = __floats2half2_rn(v0, v1);
        __half2 hb = __floats2half2_rn(v2, v3);
        o.x = *reinterpret_cast<uint32_t*>(&ha);
        o.y = *reinterpret_cast<uint32_t*>(&hb);
        *reinterpret_cast<uint2*>(reinterpret_cast<__half*>(out) + (size_t)n * 1024 + c) = o;
    }
}

// ---------------- host launcher ----------------
static inline void run_gemm_dual_tc(const __half* A, const __half* B1, const __half* B2,
                                    __half* C1, __half* C2,
                                    const float* a_s, const float* a_d,
                                    int M, int N1, int N2, int K) {
    dim3 grid((N1 + N2) / 128, (M + 127) / 128);
    gemm_f16_dual<<<grid, 256, HSMEM_BYTES>>>(A, B1, B2, C1, C2, a_s, a_d, M, N1, N2, K);
}

extern "C" void kernel_launch(void* const* d_in, const int* in_sizes, int n_in,
                              void* d_out, int out_size) {
    const float* x   = (const float*)d_in[0];
    const int*   ei  = (const int*)d_in[1];
    const float* W1  = (const float*)d_in[2];
    const float* a1s = (const float*)d_in[3];
    const float* a1d = (const float*)d_in[4];
    const float* b1  = (const float*)d_in[5];
    const float* lw1 = (const float*)d_in[6];
    const float* lb1 = (const float*)d_in[7];
    const float* W2  = (const float*)d_in[8];
    const float* a2s = (const float*)d_in[9];
    const float* a2d = (const float*)d_in[10];
    const float* b2  = (const float*)d_in[11];
    const float* lw2 = (const float*)d_in[12];
    const float* lb2 = (const float*)d_in[13];
    const float* W3  = (const float*)d_in[14];
    const float* a3s = (const float*)d_in[15];
    const float* a3d = (const float*)d_in[16];
    const float* b3  = (const float*)d_in[17];
    const float* lw3 = (const float*)d_in[18];
    const float* lb3 = (const float*)d_in[19];
    float* out = (float*)d_out;

    cudaFuncSetAttribute(gemm_f16_dual, cudaFuncAttributeMaxDynamicSharedMemorySize,
                         HSMEM_BYTES);

    void *p_h, *p_lin, *p_x1h, *p_x2h;
    cudaGetSymbolAddress(&p_h, g_h);
    cudaGetSymbolAddress(&p_lin, g_linh);
    cudaGetSymbolAddress(&p_x1h, g_x1h);
    cudaGetSymbolAddress(&p_x2h, g_x2h);
    __half* h    = (__half*)p_h;
    __half* lin  = (__half*)p_lin;
    __half* x1h  = (__half*)p_x1h;
    __half* x2h  = (__half*)p_x2h;

    void *p_w2h, *p_lw2h, *p_w3h, *p_lw3h;
    cudaGetSymbolAddress(&p_w2h, g_w2h);
    cudaGetSymbolAddress(&p_lw2h, g_lw2h);
    cudaGetSymbolAddress(&p_w3h, g_w3h);
    cudaGetSymbolAddress(&p_lw3h, g_lw3h);
    __half* w2h  = (__half*)p_w2h;
    __half* lw2h = (__half*)p_lw2h;
    __half* w3h  = (__half*)p_w3h;
    __half* lw3h = (__half*)p_lw3h;

    void *p_cnt, *p_fill;
    cudaGetSymbolAddress(&p_cnt, g_cnt);
    cudaGetSymbolAddress(&p_fill, g_fill);

    cudaMemsetAsync(p_cnt, 0, N_NODES * sizeof(int));
    cudaMemsetAsync(p_fill, 0, N_NODES * sizeof(int));

    k_f2h_count<<<F2H_BLOCKS + CNT_BLOCKS, 256>>>(W2, lw2, W3, lw3, ei);
    k_scan_one<<<1, 1024>>>();

    // ---- layer 1 GEMM (+ fused CSR scatter in tail blocks) ----
    {
        const int mtiles = (N_NODES + 127) / 128;                 // 79
        const int scat_rows = (CNT_BLOCKS + 31) / 32;             // 21
        dim3 grid((1024 + 1024) / 64, mtiles + scat_rows);
        sgemm_dual<<<grid, 256>>>(x, W1, lw1, h, lin, a1s, a1d, ei,
                                  N_NODES, 1024, 1024, 14);
    }
    gat_agg<4, false, true, __half><<<N_NODES, 256>>>(b1, lb1, x1h);

    // ---- layer 2: 1024 -> 4x256, concat, +skip, ELU ----
    run_gemm_dual_tc(x1h, w2h, lw2h, h, lin, a2s, a2d, N_NODES, 1024, 1024, 1024);
    gat_agg<4, false, true, __half><<<N_NODES, 256>>>(b2, lb2, x2h);

    // ---- layer 3: 1024 -> mean of 6x256, +skip, no ELU ----
    run_gemm_dual_tc(x2h, w3h, lw3h, h, lin, a3s, a3d, N_NODES, 1536, 256, 1024);
    gat_agg<6, true, false, float><<<N_NODES, 256>>>(b3, lb3, out);
}